// round 1
// baseline (speedup 1.0000x reference)
#include <cuda_runtime.h>
#include <math.h>
#include <stdint.h>

#define BATCH   4
#define SEQ     2048
#define NHEADS  16
#define HDIM    64
#define DIM     1024
#define MTOT    (BATCH*SEQ)        // 8192

// ---------------------------------------------------------------------------
// Scratch (device globals: allocation-free per harness rules)
// ---------------------------------------------------------------------------
__device__ float g_xq[BATCH*NHEADS*SEQ*HDIM];
__device__ float g_xk[BATCH*NHEADS*SEQ*HDIM];
__device__ float g_xv[BATCH*NHEADS*SEQ*HDIM];
__device__ float g_xo[BATCH*NHEADS*SEQ*HDIM];

// ---------------------------------------------------------------------------
// GEMM: C[M,N] = A[M,K] @ B[K,N], M=8192, N=K=1024.
//   GATHER_A : A is read from [b,h,s,d] scratch layout (for output projection)
//   SCATTER_C: C is written to [b,h,s,d] scratch layout (for QKV projections)
// 128x128 block tile, BK=16, 256 threads, 8x8 register microtile.
// ---------------------------------------------------------------------------
template<bool GATHER_A, bool SCATTER_C>
__global__ __launch_bounds__(256)
void gemm128(const float* __restrict__ A, const float* __restrict__ Bw,
             float* __restrict__ C)
{
    const int K = DIM, N = DIM;
    __shared__ float As[16][128 + 4];   // stored transposed: As[k][m]
    __shared__ float Bs[16][128];       // Bs[k][n]

    const int tid = threadIdx.x;
    const int m0 = blockIdx.y * 128;
    const int n0 = blockIdx.x * 128;
    const int ty = tid >> 4;            // 0..15
    const int tx = tid & 15;            // 0..15

    float acc[8][8];
#pragma unroll
    for (int i = 0; i < 8; i++)
#pragma unroll
        for (int j = 0; j < 8; j++) acc[i][j] = 0.f;

    for (int k0 = 0; k0 < K; k0 += 16) {
        // ---- load A tile (128 x 16) as float4, store transposed ----
#pragma unroll
        for (int r = 0; r < 2; r++) {
            int idx = tid + r * 256;          // 0..511
            int row = idx >> 2;               // 0..127
            int kq  = (idx & 3) * 4;          // 0,4,8,12
            int m   = m0 + row;
            int kg  = k0 + kq;
            const float* ap;
            if (GATHER_A) {
                int b = m >> 11, s = m & (SEQ - 1);
                int h = kg >> 6, d = kg & (HDIM - 1);
                ap = A + (((size_t)(b * NHEADS + h) * SEQ + s) * HDIM + d);
            } else {
                ap = A + (size_t)m * K + kg;
            }
            float4 av = *reinterpret_cast<const float4*>(ap);
            As[kq + 0][row] = av.x;
            As[kq + 1][row] = av.y;
            As[kq + 2][row] = av.z;
            As[kq + 3][row] = av.w;
        }
        // ---- load B tile (16 x 128) ----
#pragma unroll
        for (int r = 0; r < 2; r++) {
            int idx = tid + r * 256;          // 0..511
            int kr  = idx >> 5;               // 0..15
            int nq  = (idx & 31) * 4;         // 0..124
            float4 bv = *reinterpret_cast<const float4*>(
                Bw + (size_t)(k0 + kr) * N + n0 + nq);
            *reinterpret_cast<float4*>(&Bs[kr][nq]) = bv;
        }
        __syncthreads();

#pragma unroll
        for (int kk = 0; kk < 16; kk++) {
            float a[8], b[8];
#pragma unroll
            for (int i = 0; i < 8; i++) a[i] = As[kk][ty + i * 16];
#pragma unroll
            for (int j = 0; j < 8; j++) b[j] = Bs[kk][tx + j * 16];
#pragma unroll
            for (int i = 0; i < 8; i++)
#pragma unroll
                for (int j = 0; j < 8; j++)
                    acc[i][j] += a[i] * b[j];
        }
        __syncthreads();
    }

    // ---- epilogue ----
#pragma unroll
    for (int i = 0; i < 8; i++) {
        int m = m0 + ty + i * 16;
#pragma unroll
        for (int j = 0; j < 8; j++) {
            int n = n0 + tx + j * 16;
            if (SCATTER_C) {
                int b = m >> 11, s = m & (SEQ - 1);
                int h = n >> 6, d = n & (HDIM - 1);
                C[((size_t)(b * NHEADS + h) * SEQ + s) * HDIM + d] = acc[i][j];
            } else {
                C[(size_t)m * N + n] = acc[i][j];
            }
        }
    }
}

// ---------------------------------------------------------------------------
// Causal flash attention: per block = one (b,h) x 128-query tile.
// BQ=128, BK=64, D=64, 256 threads. Online softmax, O kept in registers.
// ---------------------------------------------------------------------------
#define BQ 128
#define BK 64

// dyn smem: Qt[64][128], Kt[64][64], Vs[64][64], Ss[128][65], alpha[128], l[128]
#define ATTN_SMEM_FLOATS (64*128 + 64*64 + 64*64 + 128*65 + 128 + 128)
#define ATTN_SMEM_BYTES  (ATTN_SMEM_FLOATS * 4)

__global__ __launch_bounds__(256)
void attn_kernel(const float* __restrict__ xq, const float* __restrict__ xk,
                 const float* __restrict__ xv, float* __restrict__ xo)
{
    extern __shared__ float sm[];
    float* Qt      = sm;                    // [d][q]  64x128 (transposed)
    float* Kt      = Qt + 64 * 128;         // [d][k]  64x64  (transposed)
    float* Vs      = Kt + 64 * 64;          // [k][d]  64x64
    float* Ss      = Vs + 64 * 64;          // [q][k]  128x65 (padded)
    float* alpha_s = Ss + 128 * 65;         // [128]
    float* l_s     = alpha_s + 128;         // [128]

    const int tid = threadIdx.x;
    const int qt  = blockIdx.x;
    const int bh  = blockIdx.y;             // b*NHEADS + h
    const float* qbase = xq + (size_t)bh * SEQ * HDIM;
    const float* kbase = xk + (size_t)bh * SEQ * HDIM;
    const float* vbase = xv + (size_t)bh * SEQ * HDIM;
    float*       obase = xo + (size_t)bh * SEQ * HDIM;

    const int q0 = qt * BQ;

    // ---- load Q tile, transposed + scaled by 1/sqrt(HDIM) ----
#pragma unroll
    for (int r = 0; r < 8; r++) {
        int idx  = tid + r * 256;           // 0..2047
        int qrow = idx >> 4;                // 0..127
        int dq   = (idx & 15) * 4;          // 0..60
        float4 v = *reinterpret_cast<const float4*>(
            qbase + (size_t)(q0 + qrow) * HDIM + dq);
        Qt[(dq + 0) * 128 + qrow] = v.x * 0.125f;
        Qt[(dq + 1) * 128 + qrow] = v.y * 0.125f;
        Qt[(dq + 2) * 128 + qrow] = v.z * 0.125f;
        Qt[(dq + 3) * 128 + qrow] = v.w * 0.125f;
    }

    const int ty = tid >> 4;                // 0..15 (q thread-row)
    const int tx = tid & 15;                // 0..15 (k / d thread-col)
    const int sr = tid >> 1;                // 0..127 (softmax row)
    const int shalf = tid & 1;              // 0/1

    float O[8][4];
#pragma unroll
    for (int i = 0; i < 8; i++)
#pragma unroll
        for (int j = 0; j < 4; j++) O[i][j] = 0.f;

    float m_prev = -INFINITY;
    float l_prev = 0.f;

    const int nkt = (q0 + BQ) / BK;         // causal tile count
    for (int kt = 0; kt < nkt; kt++) {
        const int k0 = kt * BK;
        __syncthreads();  // previous iteration done with Kt/Vs/Ss (and Qt ready)

        // ---- load K (transposed) and V (natural) ----
#pragma unroll
        for (int r = 0; r < 4; r++) {
            int idx  = tid + r * 256;       // 0..1023
            int krow = idx >> 4;            // 0..63
            int dq   = (idx & 15) * 4;
            float4 kv = *reinterpret_cast<const float4*>(
                kbase + (size_t)(k0 + krow) * HDIM + dq);
            Kt[(dq + 0) * 64 + krow] = kv.x;
            Kt[(dq + 1) * 64 + krow] = kv.y;
            Kt[(dq + 2) * 64 + krow] = kv.z;
            Kt[(dq + 3) * 64 + krow] = kv.w;
            float4 vv = *reinterpret_cast<const float4*>(
                vbase + (size_t)(k0 + krow) * HDIM + dq);
            *reinterpret_cast<float4*>(&Vs[krow * 64 + dq]) = vv;
        }
        __syncthreads();

        // ---- S = Q @ K^T  (128x64), 8x4 per thread ----
        float s_acc[8][4];
#pragma unroll
        for (int i = 0; i < 8; i++)
#pragma unroll
            for (int j = 0; j < 4; j++) s_acc[i][j] = 0.f;

#pragma unroll
        for (int kk = 0; kk < 64; kk++) {
            float a[8], b[4];
#pragma unroll
            for (int i = 0; i < 8; i++) a[i] = Qt[kk * 128 + ty + i * 16];
#pragma unroll
            for (int j = 0; j < 4; j++) b[j] = Kt[kk * 64 + tx + j * 16];
#pragma unroll
            for (int i = 0; i < 8; i++)
#pragma unroll
                for (int j = 0; j < 4; j++)
                    s_acc[i][j] += a[i] * b[j];
        }
        // write with causal mask
#pragma unroll
        for (int i = 0; i < 8; i++) {
            int qg = q0 + ty + i * 16;
#pragma unroll
            for (int j = 0; j < 4; j++) {
                int kg = k0 + tx + j * 16;
                Ss[(ty + i * 16) * 65 + tx + j * 16] =
                    (kg > qg) ? -INFINITY : s_acc[i][j];
            }
        }
        __syncthreads();

        // ---- online softmax: 2 threads per row, 32 cols each ----
        float tmax = -INFINITY;
#pragma unroll
        for (int c = 0; c < 32; c++)
            tmax = fmaxf(tmax, Ss[sr * 65 + shalf * 32 + c]);
        tmax = fmaxf(tmax, __shfl_xor_sync(0xffffffffu, tmax, 1));
        float m_new = fmaxf(m_prev, tmax);
        float alpha = __expf(m_prev - m_new);
        float psum = 0.f;
#pragma unroll
        for (int c = 0; c < 32; c++) {
            float p = __expf(Ss[sr * 65 + shalf * 32 + c] - m_new);
            Ss[sr * 65 + shalf * 32 + c] = p;
            psum += p;
        }
        psum += __shfl_xor_sync(0xffffffffu, psum, 1);
        l_prev = l_prev * alpha + psum;
        m_prev = m_new;
        if (shalf == 0) alpha_s[sr] = alpha;
        __syncthreads();

        // ---- O = O*alpha + P @ V  (128x64), 8x4 per thread ----
#pragma unroll
        for (int i = 0; i < 8; i++) {
            float al = alpha_s[ty + i * 16];
#pragma unroll
            for (int j = 0; j < 4; j++) O[i][j] *= al;
        }
#pragma unroll
        for (int kk = 0; kk < 64; kk++) {
            float p[8], v[4];
#pragma unroll
            for (int i = 0; i < 8; i++) p[i] = Ss[(ty + i * 16) * 65 + kk];
#pragma unroll
            for (int j = 0; j < 4; j++) v[j] = Vs[kk * 64 + tx + j * 16];
#pragma unroll
            for (int i = 0; i < 8; i++)
#pragma unroll
                for (int j = 0; j < 4; j++)
                    O[i][j] += p[i] * v[j];
        }
    }

    // ---- finalize ----
    if (shalf == 0) l_s[sr] = l_prev;
    __syncthreads();
#pragma unroll
    for (int i = 0; i < 8; i++) {
        float inv = 1.f / l_s[ty + i * 16];
        int qg = q0 + ty + i * 16;
#pragma unroll
        for (int j = 0; j < 4; j++)
            obase[(size_t)qg * HDIM + tx + j * 16] = O[i][j] * inv;
    }
}

// ---------------------------------------------------------------------------
// Launch
// ---------------------------------------------------------------------------
extern "C" void kernel_launch(void* const* d_in, const int* in_sizes, int n_in,
                              void* d_out, int out_size)
{
    (void)in_sizes; (void)n_in; (void)out_size;
    const float* q  = (const float*)d_in[0];
    const float* k  = (const float*)d_in[1];
    const float* v  = (const float*)d_in[2];
    const float* wq = (const float*)d_in[3];
    const float* wk = (const float*)d_in[4];
    const float* wv = (const float*)d_in[5];
    const float* wo = (const float*)d_in[6];
    float* out = (float*)d_out;

    float *xq, *xk, *xv, *xo;
    cudaGetSymbolAddress((void**)&xq, g_xq);
    cudaGetSymbolAddress((void**)&xk, g_xk);
    cudaGetSymbolAddress((void**)&xv, g_xv);
    cudaGetSymbolAddress((void**)&xo, g_xo);

    cudaFuncSetAttribute(attn_kernel,
                         cudaFuncAttributeMaxDynamicSharedMemorySize,
                         ATTN_SMEM_BYTES);

    dim3 ggrid(DIM / 128, MTOT / 128);   // (8, 64)
    gemm128<false, true><<<ggrid, 256>>>(q, wq, xq);
    gemm128<false, true><<<ggrid, 256>>>(k, wk, xk);
    gemm128<false, true><<<ggrid, 256>>>(v, wv, xv);

    dim3 agrid(SEQ / BQ, BATCH * NHEADS); // (16, 64)
    attn_kernel<<<agrid, 256, ATTN_SMEM_BYTES>>>(xq, xk, xv, xo);

    gemm128<true, false><<<ggrid, 256>>>(xo, wo, out);
}

// round 2
// speedup vs baseline: 3.4266x; 3.4266x over previous
#include <cuda_runtime.h>
#include <math.h>
#include <stdint.h>

#define BATCH   4
#define SEQ     2048
#define NHEADS  16
#define HDIM    64
#define DIM     1024
#define MTOT    (BATCH*SEQ)        // 8192

// ---------------------------------------------------------------------------
// Scratch (device globals: allocation-free per harness rules)
// ---------------------------------------------------------------------------
__device__ float g_xq[BATCH*NHEADS*SEQ*HDIM];
__device__ float g_xk[BATCH*NHEADS*SEQ*HDIM];
__device__ float g_xv[BATCH*NHEADS*SEQ*HDIM];
__device__ float g_xo[BATCH*NHEADS*SEQ*HDIM];

// ---------------------------------------------------------------------------
// Helpers: tf32 convert + mma.sync m16n8k8 tf32
// ---------------------------------------------------------------------------
__device__ __forceinline__ uint32_t f2tf32(float f) {
    uint32_t r;
    asm("cvt.rna.tf32.f32 %0, %1;" : "=r"(r) : "f"(f));
    return r;
}

__device__ __forceinline__ float fast_exp2(float x) {
    float r;
    asm("ex2.approx.f32 %0, %1;" : "=f"(r) : "f"(x));
    return r;
}

__device__ __forceinline__ void mma_tf32(float c[4],
    uint32_t a0, uint32_t a1, uint32_t a2, uint32_t a3,
    uint32_t b0, uint32_t b1)
{
    asm volatile(
        "mma.sync.aligned.m16n8k8.row.col.f32.tf32.tf32.f32 "
        "{%0,%1,%2,%3}, {%4,%5,%6,%7}, {%8,%9}, {%0,%1,%2,%3};\n"
        : "+f"(c[0]), "+f"(c[1]), "+f"(c[2]), "+f"(c[3])
        : "r"(a0), "r"(a1), "r"(a2), "r"(a3), "r"(b0), "r"(b1));
}

// ---------------------------------------------------------------------------
// TF32 tensor-core GEMM: C[M,N] = A[M,K] @ B[K,N], M=8192, N=K=1024.
// 128x128 block tile, BK=32, 256 threads (8 warps, 2x4), warp tile 64x32.
//   GATHER_A : A read from [b,h,s,d] scratch layout (output projection)
//   SCATTER_C: C written to [b,h,s,d] scratch layout (QKV projections)
// ---------------------------------------------------------------------------
template<bool GATHER_A, bool SCATTER_C>
__global__ __launch_bounds__(256, 2)
void gemm_tc(const float* __restrict__ A, const float* __restrict__ Bw,
             float* __restrict__ C)
{
    __shared__ uint32_t As[128][36];    // [m][k], BK=32 + pad 4 (conflict-free)
    __shared__ uint32_t Bs[32][136];    // [k][n], 128 + pad 8  (conflict-free)

    const int tid  = threadIdx.x;
    const int wid  = tid >> 5;
    const int lane = tid & 31;
    const int gp   = lane >> 2;         // 0..7
    const int qd   = lane & 3;          // 0..3
    const int wm   = (wid >> 2) * 64;   // warp m offset within block
    const int wn   = (wid & 3) * 32;    // warp n offset within block
    const int m0   = blockIdx.y * 128;
    const int n0   = blockIdx.x * 128;

    float acc[4][4][4];                 // [mtile][ntile][creg]
#pragma unroll
    for (int i = 0; i < 4; i++)
#pragma unroll
        for (int j = 0; j < 4; j++)
#pragma unroll
            for (int r = 0; r < 4; r++) acc[i][j][r] = 0.f;

    for (int k0 = 0; k0 < DIM; k0 += 32) {
        // ---- load A tile (128 x 32) ----
#pragma unroll
        for (int r = 0; r < 4; r++) {
            int idx = tid + r * 256;        // 0..1023
            int row = idx >> 3;             // 0..127
            int kq  = (idx & 7) * 4;        // 0..28
            int m   = m0 + row;
            int kg  = k0 + kq;
            const float* ap;
            if (GATHER_A) {
                int b = m >> 11, s = m & (SEQ - 1);
                int h = kg >> 6, d = kg & (HDIM - 1);
                ap = A + (((size_t)(b * NHEADS + h) * SEQ + s) * HDIM + d);
            } else {
                ap = A + (size_t)m * DIM + kg;
            }
            float4 av = *reinterpret_cast<const float4*>(ap);
            uint4 at;
            at.x = f2tf32(av.x); at.y = f2tf32(av.y);
            at.z = f2tf32(av.z); at.w = f2tf32(av.w);
            *reinterpret_cast<uint4*>(&As[row][kq]) = at;
        }
        // ---- load B tile (32 x 128) ----
#pragma unroll
        for (int r = 0; r < 4; r++) {
            int idx = tid + r * 256;
            int kr  = idx >> 5;             // 0..31
            int nq  = (idx & 31) * 4;       // 0..124
            float4 bv = *reinterpret_cast<const float4*>(
                Bw + (size_t)(k0 + kr) * DIM + n0 + nq);
            uint4 bt;
            bt.x = f2tf32(bv.x); bt.y = f2tf32(bv.y);
            bt.z = f2tf32(bv.z); bt.w = f2tf32(bv.w);
            *reinterpret_cast<uint4*>(&Bs[kr][nq]) = bt;
        }
        __syncthreads();

        // ---- compute: 4 k-substeps of 8 ----
#pragma unroll
        for (int ks = 0; ks < 4; ks++) {
            uint32_t af[4][4];
#pragma unroll
            for (int mt = 0; mt < 4; mt++) {
                int rr = wm + mt * 16 + gp;
                af[mt][0] = As[rr    ][ks * 8 + qd];
                af[mt][1] = As[rr + 8][ks * 8 + qd];
                af[mt][2] = As[rr    ][ks * 8 + qd + 4];
                af[mt][3] = As[rr + 8][ks * 8 + qd + 4];
            }
            uint32_t bf[4][2];
#pragma unroll
            for (int nt = 0; nt < 4; nt++) {
                bf[nt][0] = Bs[ks * 8 + qd    ][wn + nt * 8 + gp];
                bf[nt][1] = Bs[ks * 8 + qd + 4][wn + nt * 8 + gp];
            }
#pragma unroll
            for (int mt = 0; mt < 4; mt++)
#pragma unroll
                for (int nt = 0; nt < 4; nt++)
                    mma_tf32(acc[mt][nt], af[mt][0], af[mt][1], af[mt][2], af[mt][3],
                             bf[nt][0], bf[nt][1]);
        }
        __syncthreads();
    }

    // ---- epilogue: write float2 pairs ----
#pragma unroll
    for (int mt = 0; mt < 4; mt++) {
        int row0 = m0 + wm + mt * 16 + gp;
        int row1 = row0 + 8;
#pragma unroll
        for (int nt = 0; nt < 4; nt++) {
            int col = n0 + wn + nt * 8 + 2 * qd;
            float2 v0 = make_float2(acc[mt][nt][0], acc[mt][nt][1]);
            float2 v1 = make_float2(acc[mt][nt][2], acc[mt][nt][3]);
            if (SCATTER_C) {
                int h = col >> 6, d = col & (HDIM - 1);
                int b0i = row0 >> 11, s0 = row0 & (SEQ - 1);
                int b1i = row1 >> 11, s1 = row1 & (SEQ - 1);
                *reinterpret_cast<float2*>(
                    C + (((size_t)(b0i * NHEADS + h) * SEQ + s0) * HDIM + d)) = v0;
                *reinterpret_cast<float2*>(
                    C + (((size_t)(b1i * NHEADS + h) * SEQ + s1) * HDIM + d)) = v1;
            } else {
                *reinterpret_cast<float2*>(C + (size_t)row0 * DIM + col) = v0;
                *reinterpret_cast<float2*>(C + (size_t)row1 * DIM + col) = v1;
            }
        }
    }
}

// ---------------------------------------------------------------------------
// Causal flash attention on tensor cores (TF32 mma), register softmax.
// BQ=128, BK=64, D=64, 256 threads (8 warps). Warp w owns q rows [16w,16w+16).
// ---------------------------------------------------------------------------
#define BQ 128
#define BK 64

// dyn smem words: Qs[128][68] + Ks[64][68] + Vs[64][68] + Ss[128][68]
#define QS_OFF  0
#define KS_OFF  (128*68)
#define VS_OFF  (KS_OFF + 64*68)
#define SS_OFF  (VS_OFF + 64*68)
#define ATTN_SMEM_WORDS (SS_OFF + 128*68)
#define ATTN_SMEM_BYTES (ATTN_SMEM_WORDS * 4)

__global__ __launch_bounds__(256, 2)
void attn_tc(const float* __restrict__ xq, const float* __restrict__ xk,
             const float* __restrict__ xv, float* __restrict__ xo)
{
    extern __shared__ uint32_t sm[];
    uint32_t* Qs = sm + QS_OFF;   // [q][d] tf32, stride 68
    uint32_t* Ks = sm + KS_OFF;   // [k][d] tf32, stride 68
    uint32_t* Vs = sm + VS_OFF;   // [k][d] tf32, stride 68
    uint32_t* Ss = sm + SS_OFF;   // [q][kk] tf32 P, stride 68 (warp-private rows)

    const int tid  = threadIdx.x;
    const int wid  = tid >> 5;
    const int lane = tid & 31;
    const int gp   = lane >> 2;
    const int qd   = lane & 3;

    const int qt = blockIdx.x;
    const int bh = blockIdx.y;
    const float* qbase = xq + (size_t)bh * SEQ * HDIM;
    const float* kbase = xk + (size_t)bh * SEQ * HDIM;
    const float* vbase = xv + (size_t)bh * SEQ * HDIM;
    float*       obase = xo + (size_t)bh * SEQ * HDIM;
    const int q0 = qt * BQ;

    // ---- load Q tile (128 x 64), scale by 1/sqrt(HDIM) * log2(e), tf32 ----
    const float qscale = 0.125f * 1.44269504088896f;
#pragma unroll
    for (int r = 0; r < 8; r++) {
        int idx  = tid + r * 256;           // 0..2047
        int qrow = idx >> 4;                // 0..127
        int dq   = (idx & 15) * 4;          // 0..60
        float4 v = *reinterpret_cast<const float4*>(
            qbase + (size_t)(q0 + qrow) * HDIM + dq);
        uint4 t;
        t.x = f2tf32(v.x * qscale); t.y = f2tf32(v.y * qscale);
        t.z = f2tf32(v.z * qscale); t.w = f2tf32(v.w * qscale);
        *reinterpret_cast<uint4*>(&Qs[qrow * 68 + dq]) = t;
    }

    float ofrag[8][4];                      // [ntile(d)][creg]
#pragma unroll
    for (int nt = 0; nt < 8; nt++)
#pragma unroll
        for (int r = 0; r < 4; r++) ofrag[nt][r] = 0.f;

    float m0s = -INFINITY, m1s = -INFINITY; // running max, rows r0/r1
    float l0s = 0.f, l1s = 0.f;             // running sum

    const int qrow0 = q0 + 16 * wid + gp;   // this thread's first q row
    const int qrow1 = qrow0 + 8;

    const int nkt = (q0 + BQ) / BK;
    for (int kt = 0; kt < nkt; kt++) {
        const int k0 = kt * BK;
        __syncthreads();                    // prev iter done with Ks/Vs

        // ---- load K,V tiles (64 x 64 each), tf32 ----
#pragma unroll
        for (int r = 0; r < 4; r++) {
            int idx  = tid + r * 256;       // 0..1023
            int krow = idx >> 4;            // 0..63
            int dq   = (idx & 15) * 4;
            float4 kv = *reinterpret_cast<const float4*>(
                kbase + (size_t)(k0 + krow) * HDIM + dq);
            uint4 ktv;
            ktv.x = f2tf32(kv.x); ktv.y = f2tf32(kv.y);
            ktv.z = f2tf32(kv.z); ktv.w = f2tf32(kv.w);
            *reinterpret_cast<uint4*>(&Ks[krow * 68 + dq]) = ktv;
            float4 vv = *reinterpret_cast<const float4*>(
                vbase + (size_t)(k0 + krow) * HDIM + dq);
            uint4 vtv;
            vtv.x = f2tf32(vv.x); vtv.y = f2tf32(vv.y);
            vtv.z = f2tf32(vv.z); vtv.w = f2tf32(vv.w);
            *reinterpret_cast<uint4*>(&Vs[krow * 68 + dq]) = vtv;
        }
        __syncthreads();

        // ---- S = Q @ K^T : warp computes 16(q) x 64(k) ----
        float sfrag[8][4];
#pragma unroll
        for (int nt = 0; nt < 8; nt++)
#pragma unroll
            for (int r = 0; r < 4; r++) sfrag[nt][r] = 0.f;

#pragma unroll
        for (int ks = 0; ks < 8; ks++) {
            int rr = 16 * wid + gp;
            uint32_t a0 = Qs[(rr    ) * 68 + ks * 8 + qd];
            uint32_t a1 = Qs[(rr + 8) * 68 + ks * 8 + qd];
            uint32_t a2 = Qs[(rr    ) * 68 + ks * 8 + qd + 4];
            uint32_t a3 = Qs[(rr + 8) * 68 + ks * 8 + qd + 4];
#pragma unroll
            for (int nt = 0; nt < 8; nt++) {
                uint32_t b0 = Ks[(nt * 8 + gp) * 68 + ks * 8 + qd];
                uint32_t b1 = Ks[(nt * 8 + gp) * 68 + ks * 8 + qd + 4];
                mma_tf32(sfrag[nt], a0, a1, a2, a3, b0, b1);
            }
        }

        // ---- causal mask (register-side) ----
        if (k0 + BK - 1 > q0 + 16 * wid) {
#pragma unroll
            for (int nt = 0; nt < 8; nt++) {
                int c0 = k0 + nt * 8 + 2 * qd;
                if (c0     > qrow0) sfrag[nt][0] = -1e30f;
                if (c0 + 1 > qrow0) sfrag[nt][1] = -1e30f;
                if (c0     > qrow1) sfrag[nt][2] = -1e30f;
                if (c0 + 1 > qrow1) sfrag[nt][3] = -1e30f;
            }
        }

        // ---- online softmax in registers (base-2) ----
        float tmax0 = -INFINITY, tmax1 = -INFINITY;
#pragma unroll
        for (int nt = 0; nt < 8; nt++) {
            tmax0 = fmaxf(tmax0, fmaxf(sfrag[nt][0], sfrag[nt][1]));
            tmax1 = fmaxf(tmax1, fmaxf(sfrag[nt][2], sfrag[nt][3]));
        }
        tmax0 = fmaxf(tmax0, __shfl_xor_sync(0xffffffffu, tmax0, 1));
        tmax0 = fmaxf(tmax0, __shfl_xor_sync(0xffffffffu, tmax0, 2));
        tmax1 = fmaxf(tmax1, __shfl_xor_sync(0xffffffffu, tmax1, 1));
        tmax1 = fmaxf(tmax1, __shfl_xor_sync(0xffffffffu, tmax1, 2));

        float mn0 = fmaxf(m0s, tmax0);
        float mn1 = fmaxf(m1s, tmax1);
        float alpha0 = fast_exp2(m0s - mn0);   // m0s=-inf first iter -> 0
        float alpha1 = fast_exp2(m1s - mn1);
        m0s = mn0; m1s = mn1;

        float rs0 = 0.f, rs1 = 0.f;
        int rr = 16 * wid + gp;
#pragma unroll
        for (int nt = 0; nt < 8; nt++) {
            float p0 = fast_exp2(sfrag[nt][0] - mn0);
            float p1 = fast_exp2(sfrag[nt][1] - mn0);
            float p2 = fast_exp2(sfrag[nt][2] - mn1);
            float p3 = fast_exp2(sfrag[nt][3] - mn1);
            rs0 += p0 + p1;
            rs1 += p2 + p3;
            uint2 w0 = make_uint2(f2tf32(p0), f2tf32(p1));
            uint2 w1 = make_uint2(f2tf32(p2), f2tf32(p3));
            *reinterpret_cast<uint2*>(&Ss[(rr    ) * 68 + nt * 8 + 2 * qd]) = w0;
            *reinterpret_cast<uint2*>(&Ss[(rr + 8) * 68 + nt * 8 + 2 * qd]) = w1;
        }
        rs0 += __shfl_xor_sync(0xffffffffu, rs0, 1);
        rs0 += __shfl_xor_sync(0xffffffffu, rs0, 2);
        rs1 += __shfl_xor_sync(0xffffffffu, rs1, 1);
        rs1 += __shfl_xor_sync(0xffffffffu, rs1, 2);
        l0s = l0s * alpha0 + rs0;
        l1s = l1s * alpha1 + rs1;

        // rescale O
#pragma unroll
        for (int nt = 0; nt < 8; nt++) {
            ofrag[nt][0] *= alpha0; ofrag[nt][1] *= alpha0;
            ofrag[nt][2] *= alpha1; ofrag[nt][3] *= alpha1;
        }
        __syncwarp();                       // P visible within warp

        // ---- O += P @ V : 16(q) x 64(d), K=64(kk) ----
#pragma unroll
        for (int ks = 0; ks < 8; ks++) {
            uint32_t a0 = Ss[(rr    ) * 68 + ks * 8 + qd];
            uint32_t a1 = Ss[(rr + 8) * 68 + ks * 8 + qd];
            uint32_t a2 = Ss[(rr    ) * 68 + ks * 8 + qd + 4];
            uint32_t a3 = Ss[(rr + 8) * 68 + ks * 8 + qd + 4];
#pragma unroll
            for (int nt = 0; nt < 8; nt++) {
                uint32_t b0 = Vs[(ks * 8 + qd    ) * 68 + nt * 8 + gp];
                uint32_t b1 = Vs[(ks * 8 + qd + 4) * 68 + nt * 8 + gp];
                mma_tf32(ofrag[nt], a0, a1, a2, a3, b0, b1);
            }
        }
    }

    // ---- finalize: divide by l, write out ----
    float inv0 = 1.f / l0s;
    float inv1 = 1.f / l1s;
#pragma unroll
    for (int nt = 0; nt < 8; nt++) {
        int col = nt * 8 + 2 * qd;
        float2 v0 = make_float2(ofrag[nt][0] * inv0, ofrag[nt][1] * inv0);
        float2 v1 = make_float2(ofrag[nt][2] * inv1, ofrag[nt][3] * inv1);
        *reinterpret_cast<float2*>(obase + (size_t)qrow0 * HDIM + col) = v0;
        *reinterpret_cast<float2*>(obase + (size_t)qrow1 * HDIM + col) = v1;
    }
}

// ---------------------------------------------------------------------------
// Launch
// ---------------------------------------------------------------------------
extern "C" void kernel_launch(void* const* d_in, const int* in_sizes, int n_in,
                              void* d_out, int out_size)
{
    (void)in_sizes; (void)n_in; (void)out_size;
    const float* q  = (const float*)d_in[0];
    const float* k  = (const float*)d_in[1];
    const float* v  = (const float*)d_in[2];
    const float* wq = (const float*)d_in[3];
    const float* wk = (const float*)d_in[4];
    const float* wv = (const float*)d_in[5];
    const float* wo = (const float*)d_in[6];
    float* out = (float*)d_out;

    float *xq, *xk, *xv, *xo;
    cudaGetSymbolAddress((void**)&xq, g_xq);
    cudaGetSymbolAddress((void**)&xk, g_xk);
    cudaGetSymbolAddress((void**)&xv, g_xv);
    cudaGetSymbolAddress((void**)&xo, g_xo);

    cudaFuncSetAttribute(attn_tc,
                         cudaFuncAttributeMaxDynamicSharedMemorySize,
                         ATTN_SMEM_BYTES);

    dim3 ggrid(DIM / 128, MTOT / 128);     // (8, 64)
    gemm_tc<false, true><<<ggrid, 256>>>(q, wq, xq);
    gemm_tc<false, true><<<ggrid, 256>>>(k, wk, xk);
    gemm_tc<false, true><<<ggrid, 256>>>(v, wv, xv);

    dim3 agrid(SEQ / BQ, BATCH * NHEADS);  // (16, 64)
    attn_tc<<<agrid, 256, ATTN_SMEM_BYTES>>>(xq, xk, xv, xo);

    gemm_tc<true, false><<<ggrid, 256>>>(xo, wo, out);
}

// round 6
// speedup vs baseline: 3.8571x; 1.1256x over previous
#include <cuda_runtime.h>
#include <math.h>
#include <stdint.h>

#define BATCH   4
#define SEQ     2048
#define NHEADS  16
#define HDIM    64
#define DIM     1024
#define MTOT    (BATCH*SEQ)        // 8192

// ---------------------------------------------------------------------------
// Scratch (device globals: allocation-free per harness rules)
// ---------------------------------------------------------------------------
__device__ float g_xq[BATCH*NHEADS*SEQ*HDIM];
__device__ float g_xk[BATCH*NHEADS*SEQ*HDIM];
__device__ float g_xv[BATCH*NHEADS*SEQ*HDIM];
__device__ float g_xo[BATCH*NHEADS*SEQ*HDIM];
__device__ float g_wt[4*DIM*DIM];       // tf32-rounded weights [k][n]

// ---------------------------------------------------------------------------
// PTX helpers
// ---------------------------------------------------------------------------
__device__ __forceinline__ uint32_t f2tf32(float f) {
    uint32_t r;
    asm("cvt.rna.tf32.f32 %0, %1;" : "=r"(r) : "f"(f));
    return r;
}
__device__ __forceinline__ float fast_exp2(float x) {
    float r;
    asm("ex2.approx.f32 %0, %1;" : "=f"(r) : "f"(x));
    return r;
}
__device__ __forceinline__ uint32_t smem_u32(const void* p) {
    uint32_t a;
    asm("{ .reg .u64 t; cvta.to.shared.u64 t, %1; cvt.u32.u64 %0, t; }"
        : "=r"(a) : "l"(p));
    return a;
}
__device__ __forceinline__ void cp16(uint32_t dst, const void* src) {
    asm volatile("cp.async.cg.shared.global [%0], [%1], 16;"
                 :: "r"(dst), "l"(src) : "memory");
}
__device__ __forceinline__ void cp_commit() {
    asm volatile("cp.async.commit_group;" ::: "memory");
}
template<int N> __device__ __forceinline__ void cp_wait() {
    asm volatile("cp.async.wait_group %0;" :: "n"(N) : "memory");
}
__device__ __forceinline__ void mma_tf32(float c[4],
    uint32_t a0, uint32_t a1, uint32_t a2, uint32_t a3,
    uint32_t b0, uint32_t b1)
{
    asm volatile(
        "mma.sync.aligned.m16n8k8.row.col.f32.tf32.tf32.f32 "
        "{%0,%1,%2,%3}, {%4,%5,%6,%7}, {%8,%9}, {%0,%1,%2,%3};\n"
        : "+f"(c[0]), "+f"(c[1]), "+f"(c[2]), "+f"(c[3])
        : "r"(a0), "r"(a1), "r"(a2), "r"(a3), "r"(b0), "r"(b1));
}

// ---------------------------------------------------------------------------
// Weight rounding: o[i] = rna_tf32(w[i] * scale)   (qscale*log2e folded for wq)
// ---------------------------------------------------------------------------
__global__ void wround(const float* __restrict__ w, float* __restrict__ o,
                       float scale)
{
    int i = (blockIdx.x * blockDim.x + threadIdx.x) * 4;
    float4 v = *reinterpret_cast<const float4*>(w + i);
    uint4 t;
    t.x = f2tf32(v.x * scale); t.y = f2tf32(v.y * scale);
    t.z = f2tf32(v.z * scale); t.w = f2tf32(v.w * scale);
    *reinterpret_cast<uint4*>(o + i) = t;
}

// ---------------------------------------------------------------------------
// TF32 mma.sync GEMM with 3-stage cp.async pipeline.
// C[M,N] = A[M,K] @ B[K,N], M=8192, N=K=1024. 128x128 tile, BK=32,
// 256 threads (8 warps 2x4), warp tile 64x32.
//   CVT_A    : A is raw fp32 -> cvt.rna in fragment load (QKV projections)
//   GATHER_A : A read from [b,h,s,d] scratch (output projection)
//   SCATTER_C: C written to [b,h,s,d] scratch, tf32-rounded (QKV projections)
// ---------------------------------------------------------------------------
#define GM_AST 36                         // A row stride (words)
#define GM_BST 136                        // B row stride (words)
#define GM_STAGE_W (128*GM_AST + 32*GM_BST)  // 8960 words
#define GM_STAGE_B (GM_STAGE_W*4)            // 35840 bytes
#define GM_SMEM    (3*GM_STAGE_B)            // 107520 bytes

template<bool CVT_A, bool GATHER_A, bool SCATTER_C>
__global__ __launch_bounds__(256, 2)
void gemm_mma(const float* __restrict__ A, const float* __restrict__ Bt,
              float* __restrict__ C)
{
    extern __shared__ char smem[];
    const uint32_t sb = smem_u32(smem);
    const int tid  = threadIdx.x;
    const int wid  = tid >> 5;
    const int lane = tid & 31;
    const int gp   = lane >> 2;
    const int qd   = lane & 3;
    const int wm   = (wid >> 2) * 64;
    const int wn   = (wid & 3) * 32;
    const int m0   = blockIdx.y * 128;
    const int n0   = blockIdx.x * 128;

    auto load_stage = [&](int ck, int s) {
        const int k0 = ck * 32;
        const uint32_t ab = sb + s * GM_STAGE_B;
        const uint32_t bb = ab + 128 * GM_AST * 4;
        // A: 128 rows x 8 chunks of 16B
#pragma unroll
        for (int i = 0; i < 4; i++) {
            int idx = tid + i * 256;
            int row = idx >> 3;
            int c   = idx & 7;
            int m = m0 + row, kg = k0 + c * 4;
            const float* ap;
            if (GATHER_A) {
                int b = m >> 11, sq = m & (SEQ - 1);
                int h = kg >> 6, d = kg & (HDIM - 1);
                ap = A + (((size_t)(b * NHEADS + h) * SEQ + sq) * HDIM + d);
            } else {
                ap = A + (size_t)m * DIM + kg;
            }
            cp16(ab + (uint32_t)row * 144 + c * 16, ap);
        }
        // B: 32 rows x 32 chunks of 16B
#pragma unroll
        for (int i = 0; i < 4; i++) {
            int idx = tid + i * 256;
            int row = idx >> 5;
            int c   = idx & 31;
            cp16(bb + (uint32_t)row * 544 + c * 16,
                 Bt + (size_t)(k0 + row) * DIM + n0 + c * 4);
        }
    };

    load_stage(0, 0); cp_commit();
    load_stage(1, 1); cp_commit();

    float acc[4][4][4];
#pragma unroll
    for (int i = 0; i < 4; i++)
#pragma unroll
        for (int j = 0; j < 4; j++)
#pragma unroll
            for (int r = 0; r < 4; r++) acc[i][j][r] = 0.f;

    int cs = 0, ls = 2;
    for (int j = 0; j < 32; j++) {
        cp_wait<1>();
        __syncthreads();
        if (j + 2 < 32) load_stage(j + 2, ls);
        cp_commit();

        const uint32_t* As = reinterpret_cast<const uint32_t*>(smem) + cs * GM_STAGE_W;
        const uint32_t* Bs = As + 128 * GM_AST;
#pragma unroll
        for (int ks = 0; ks < 4; ks++) {
            uint32_t af[4][4];
#pragma unroll
            for (int mt = 0; mt < 4; mt++) {
                int r0 = (wm + mt * 16 + gp) * GM_AST + ks * 8 + qd;
                uint32_t v0 = As[r0];
                uint32_t v1 = As[r0 + 8 * GM_AST];
                uint32_t v2 = As[r0 + 4];
                uint32_t v3 = As[r0 + 8 * GM_AST + 4];
                if (CVT_A) {
                    af[mt][0] = f2tf32(__uint_as_float(v0));
                    af[mt][1] = f2tf32(__uint_as_float(v1));
                    af[mt][2] = f2tf32(__uint_as_float(v2));
                    af[mt][3] = f2tf32(__uint_as_float(v3));
                } else {
                    af[mt][0] = v0; af[mt][1] = v1; af[mt][2] = v2; af[mt][3] = v3;
                }
            }
            uint32_t bf[4][2];
#pragma unroll
            for (int nt = 0; nt < 4; nt++) {
                bf[nt][0] = Bs[(ks * 8 + qd    ) * GM_BST + wn + nt * 8 + gp];
                bf[nt][1] = Bs[(ks * 8 + qd + 4) * GM_BST + wn + nt * 8 + gp];
            }
#pragma unroll
            for (int mt = 0; mt < 4; mt++)
#pragma unroll
                for (int nt = 0; nt < 4; nt++)
                    mma_tf32(acc[mt][nt], af[mt][0], af[mt][1], af[mt][2], af[mt][3],
                             bf[nt][0], bf[nt][1]);
        }
        cs = (cs == 2) ? 0 : cs + 1;
        ls = (ls == 2) ? 0 : ls + 1;
    }

    // ---- epilogue ----
#pragma unroll
    for (int mt = 0; mt < 4; mt++) {
        int row0 = m0 + wm + mt * 16 + gp;
        int row1 = row0 + 8;
#pragma unroll
        for (int nt = 0; nt < 4; nt++) {
            int col = n0 + wn + nt * 8 + 2 * qd;
            float2 v0, v1;
            if (SCATTER_C) {
                v0 = make_float2(__uint_as_float(f2tf32(acc[mt][nt][0])),
                                 __uint_as_float(f2tf32(acc[mt][nt][1])));
                v1 = make_float2(__uint_as_float(f2tf32(acc[mt][nt][2])),
                                 __uint_as_float(f2tf32(acc[mt][nt][3])));
                int h = col >> 6, d = col & (HDIM - 1);
                int b0i = row0 >> 11, s0 = row0 & (SEQ - 1);
                int b1i = row1 >> 11, s1 = row1 & (SEQ - 1);
                *reinterpret_cast<float2*>(
                    C + (((size_t)(b0i * NHEADS + h) * SEQ + s0) * HDIM + d)) = v0;
                *reinterpret_cast<float2*>(
                    C + (((size_t)(b1i * NHEADS + h) * SEQ + s1) * HDIM + d)) = v1;
            } else {
                v0 = make_float2(acc[mt][nt][0], acc[mt][nt][1]);
                v1 = make_float2(acc[mt][nt][2], acc[mt][nt][3]);
                *reinterpret_cast<float2*>(C + (size_t)row0 * DIM + col) = v0;
                *reinterpret_cast<float2*>(C + (size_t)row1 * DIM + col) = v1;
            }
        }
    }
}

// ---------------------------------------------------------------------------
// Causal flash attention, TF32 mma.sync, register softmax, register-shuffle
// P->A-fragment pass (no S smem), double-buffered cp.async K/V.
// Inputs xq (pre-scaled by 1/8*log2e), xk, xv are pre-rounded tf32.
// BQ=128, BK=64, 256 threads; warp w owns q rows [16w, 16w+16).
// ---------------------------------------------------------------------------
#define BQ 128
#define BK 64
#define AT_QW     (128*68)
#define AT_KVW    (64*68)
#define AT_STAGEW (2*AT_KVW)
#define AT_SMEM_BYTES ((AT_QW + 2*AT_STAGEW)*4)   // 104448

__global__ __launch_bounds__(256, 2)
void attn_tc(const float* __restrict__ xq, const float* __restrict__ xk,
             const float* __restrict__ xv, float* __restrict__ xo)
{
    extern __shared__ uint32_t sm[];
    uint32_t* Qs = sm;
    const uint32_t sb = smem_u32(sm);

    const int tid  = threadIdx.x;
    const int wid  = tid >> 5;
    const int lane = tid & 31;
    const int gp   = lane >> 2;
    const int qd   = lane & 3;

    const int qt = (int)gridDim.x - 1 - (int)blockIdx.x;  // heavy tiles first
    const int bh = blockIdx.y;
    const float* qbase = xq + (size_t)bh * SEQ * HDIM;
    const float* kbase = xk + (size_t)bh * SEQ * HDIM;
    const float* vbase = xv + (size_t)bh * SEQ * HDIM;
    float*       obase = xo + (size_t)bh * SEQ * HDIM;
    const int q0 = qt * BQ;

    auto load_kv = [&](int kt_, int s) {
        const int k0_ = kt_ * BK;
        const uint32_t kb = sb + (AT_QW + s * AT_STAGEW) * 4;
        const uint32_t vb = kb + AT_KVW * 4;
#pragma unroll
        for (int i = 0; i < 4; i++) {
            int idx = tid + i * 256;
            int row = idx >> 4;
            int c   = idx & 15;
            cp16(kb + (uint32_t)row * 272 + c * 16,
                 kbase + (size_t)(k0_ + row) * HDIM + c * 4);
        }
#pragma unroll
        for (int i = 0; i < 4; i++) {
            int idx = tid + i * 256;
            int row = idx >> 4;
            int c   = idx & 15;
            cp16(vb + (uint32_t)row * 272 + c * 16,
                 vbase + (size_t)(k0_ + row) * HDIM + c * 4);
        }
    };

    // prologue: Q + K/V tile 0, single group
#pragma unroll
    for (int i = 0; i < 8; i++) {
        int idx = tid + i * 256;
        int row = idx >> 4;
        int c   = idx & 15;
        cp16(sb + (uint32_t)row * 272 + c * 16,
             qbase + (size_t)(q0 + row) * HDIM + c * 4);
    }
    load_kv(0, 0);
    cp_commit();

    float ofrag[8][4];
#pragma unroll
    for (int nt = 0; nt < 8; nt++)
#pragma unroll
        for (int r = 0; r < 4; r++) ofrag[nt][r] = 0.f;

    float m0s = -INFINITY, m1s = -INFINITY;
    float l0s = 0.f, l1s = 0.f;

    const int rr = 16 * wid + gp;
    const int qrow0 = q0 + rr;
    const int qrow1 = qrow0 + 8;

    const int nkt = (q0 + BQ) / BK;
    for (int kt = 0; kt < nkt; kt++) {
        const int k0 = kt * BK;
        __syncthreads();                 // buf[(kt+1)&1] free (compute kt-1 done)
        if (kt + 1 < nkt) {
            load_kv(kt + 1, (kt + 1) & 1);
            cp_commit();
            cp_wait<1>();
        } else {
            cp_wait<0>();
        }
        __syncthreads();                 // tile kt visible to all

        const uint32_t* Kst = sm + AT_QW + (kt & 1) * AT_STAGEW;
        const uint32_t* Vst = Kst + AT_KVW;

        // ---- S = Q @ K^T : 16(q) x 64(k) per warp ----
        float sfrag[8][4];
#pragma unroll
        for (int nt = 0; nt < 8; nt++)
#pragma unroll
            for (int r = 0; r < 4; r++) sfrag[nt][r] = 0.f;

#pragma unroll
        for (int ks = 0; ks < 8; ks++) {
            uint32_t a0 = Qs[(rr    ) * 68 + ks * 8 + qd];
            uint32_t a1 = Qs[(rr + 8) * 68 + ks * 8 + qd];
            uint32_t a2 = Qs[(rr    ) * 68 + ks * 8 + qd + 4];
            uint32_t a3 = Qs[(rr + 8) * 68 + ks * 8 + qd + 4];
#pragma unroll
            for (int nt = 0; nt < 8; nt++) {
                uint32_t b0 = Kst[(nt * 8 + gp) * 68 + ks * 8 + qd];
                uint32_t b1 = Kst[(nt * 8 + gp) * 68 + ks * 8 + qd + 4];
                mma_tf32(sfrag[nt], a0, a1, a2, a3, b0, b1);
            }
        }

        // ---- causal mask ----
        if (k0 + BK - 1 > q0 + 16 * wid) {
#pragma unroll
            for (int nt = 0; nt < 8; nt++) {
                int c0 = k0 + nt * 8 + 2 * qd;
                if (c0     > qrow0) sfrag[nt][0] = -1e30f;
                if (c0 + 1 > qrow0) sfrag[nt][1] = -1e30f;
                if (c0     > qrow1) sfrag[nt][2] = -1e30f;
                if (c0 + 1 > qrow1) sfrag[nt][3] = -1e30f;
            }
        }

        // ---- online softmax in registers (base-2) ----
        float tmax0 = -INFINITY, tmax1 = -INFINITY;
#pragma unroll
        for (int nt = 0; nt < 8; nt++) {
            tmax0 = fmaxf(tmax0, fmaxf(sfrag[nt][0], sfrag[nt][1]));
            tmax1 = fmaxf(tmax1, fmaxf(sfrag[nt][2], sfrag[nt][3]));
        }
        tmax0 = fmaxf(tmax0, __shfl_xor_sync(0xffffffffu, tmax0, 1));
        tmax0 = fmaxf(tmax0, __shfl_xor_sync(0xffffffffu, tmax0, 2));
        tmax1 = fmaxf(tmax1, __shfl_xor_sync(0xffffffffu, tmax1, 1));
        tmax1 = fmaxf(tmax1, __shfl_xor_sync(0xffffffffu, tmax1, 2));

        float mn0 = fmaxf(m0s, tmax0);
        float mn1 = fmaxf(m1s, tmax1);
        float alpha0 = fast_exp2(m0s - mn0);
        float alpha1 = fast_exp2(m1s - mn1);
        m0s = mn0; m1s = mn1;

        float rs0 = 0.f, rs1 = 0.f;
#pragma unroll
        for (int nt = 0; nt < 8; nt++) {
            float p0 = fast_exp2(sfrag[nt][0] - mn0);
            float p1 = fast_exp2(sfrag[nt][1] - mn0);
            float p2 = fast_exp2(sfrag[nt][2] - mn1);
            float p3 = fast_exp2(sfrag[nt][3] - mn1);
            rs0 += p0 + p1;
            rs1 += p2 + p3;
            sfrag[nt][0] = __uint_as_float(f2tf32(p0));
            sfrag[nt][1] = __uint_as_float(f2tf32(p1));
            sfrag[nt][2] = __uint_as_float(f2tf32(p2));
            sfrag[nt][3] = __uint_as_float(f2tf32(p3));
        }
        rs0 += __shfl_xor_sync(0xffffffffu, rs0, 1);
        rs0 += __shfl_xor_sync(0xffffffffu, rs0, 2);
        rs1 += __shfl_xor_sync(0xffffffffu, rs1, 1);
        rs1 += __shfl_xor_sync(0xffffffffu, rs1, 2);
        l0s = l0s * alpha0 + rs0;
        l1s = l1s * alpha1 + rs1;

#pragma unroll
        for (int nt = 0; nt < 8; nt++) {
            ofrag[nt][0] *= alpha0; ofrag[nt][1] *= alpha0;
            ofrag[nt][2] *= alpha1; ofrag[nt][3] *= alpha1;
        }

        // ---- O += P @ V : P C-frag -> A-frag via register shuffle ----
        const int src0 = (gp << 2) + (qd >> 1);
        const int src2 = src0 + 2;
        const bool odd = (qd & 1);
#pragma unroll
        for (int ks = 0; ks < 8; ks++) {
            float t00 = __shfl_sync(0xffffffffu, sfrag[ks][0], src0);
            float t01 = __shfl_sync(0xffffffffu, sfrag[ks][1], src0);
            float t10 = __shfl_sync(0xffffffffu, sfrag[ks][2], src0);
            float t11 = __shfl_sync(0xffffffffu, sfrag[ks][3], src0);
            float t20 = __shfl_sync(0xffffffffu, sfrag[ks][0], src2);
            float t21 = __shfl_sync(0xffffffffu, sfrag[ks][1], src2);
            float t30 = __shfl_sync(0xffffffffu, sfrag[ks][2], src2);
            float t31 = __shfl_sync(0xffffffffu, sfrag[ks][3], src2);
            uint32_t a0 = __float_as_uint(odd ? t01 : t00);
            uint32_t a1 = __float_as_uint(odd ? t11 : t10);
            uint32_t a2 = __float_as_uint(odd ? t21 : t20);
            uint32_t a3 = __float_as_uint(odd ? t31 : t30);
#pragma unroll
            for (int nt = 0; nt < 8; nt++) {
                uint32_t b0 = Vst[(ks * 8 + qd    ) * 68 + nt * 8 + gp];
                uint32_t b1 = Vst[(ks * 8 + qd + 4) * 68 + nt * 8 + gp];
                mma_tf32(ofrag[nt], a0, a1, a2, a3, b0, b1);
            }
        }
    }

    // ---- finalize: divide by l, round to tf32 (final GEMM reads raw) ----
    float inv0 = 1.f / l0s;
    float inv1 = 1.f / l1s;
#pragma unroll
    for (int nt = 0; nt < 8; nt++) {
        int col = nt * 8 + 2 * qd;
        uint2 v0 = make_uint2(f2tf32(ofrag[nt][0] * inv0),
                              f2tf32(ofrag[nt][1] * inv0));
        uint2 v1 = make_uint2(f2tf32(ofrag[nt][2] * inv1),
                              f2tf32(ofrag[nt][3] * inv1));
        *reinterpret_cast<uint2*>(obase + (size_t)qrow0 * HDIM + col) = v0;
        *reinterpret_cast<uint2*>(obase + (size_t)qrow1 * HDIM + col) = v1;
    }
}

// ---------------------------------------------------------------------------
// Launch
// ---------------------------------------------------------------------------
extern "C" void kernel_launch(void* const* d_in, const int* in_sizes, int n_in,
                              void* d_out, int out_size)
{
    (void)in_sizes; (void)n_in; (void)out_size;
    const float* q  = (const float*)d_in[0];
    const float* k  = (const float*)d_in[1];
    const float* v  = (const float*)d_in[2];
    const float* wq = (const float*)d_in[3];
    const float* wk = (const float*)d_in[4];
    const float* wv = (const float*)d_in[5];
    const float* wo = (const float*)d_in[6];
    float* out = (float*)d_out;

    float *xq, *xk, *xv, *xo, *wt;
    cudaGetSymbolAddress((void**)&xq, g_xq);
    cudaGetSymbolAddress((void**)&xk, g_xk);
    cudaGetSymbolAddress((void**)&xv, g_xv);
    cudaGetSymbolAddress((void**)&xo, g_xo);
    cudaGetSymbolAddress((void**)&wt, g_wt);

    cudaFuncSetAttribute(attn_tc, cudaFuncAttributeMaxDynamicSharedMemorySize,
                         AT_SMEM_BYTES);
    cudaFuncSetAttribute(gemm_mma<true, false, true>,
                         cudaFuncAttributeMaxDynamicSharedMemorySize, GM_SMEM);
    cudaFuncSetAttribute(gemm_mma<false, true, false>,
                         cudaFuncAttributeMaxDynamicSharedMemorySize, GM_SMEM);

    const float qscale = 0.125f * 1.44269504088896f;   // 1/sqrt(64) * log2(e)
    const int wgrid = DIM * DIM / (4 * 256);           // 1024
    wround<<<wgrid, 256>>>(wq, wt + 0 * DIM * DIM, qscale);
    wround<<<wgrid, 256>>>(wk, wt + 1 * DIM * DIM, 1.0f);
    wround<<<wgrid, 256>>>(wv, wt + 2 * DIM * DIM, 1.0f);
    wround<<<wgrid, 256>>>(wo, wt + 3 * DIM * DIM, 1.0f);

    dim3 ggrid(DIM / 128, MTOT / 128);   // (8, 64)
    gemm_mma<true, false, true><<<ggrid, 256, GM_SMEM>>>(q, wt + 0 * DIM * DIM, xq);
    gemm_mma<true, false, true><<<ggrid, 256, GM_SMEM>>>(k, wt + 1 * DIM * DIM, xk);
    gemm_mma<true, false, true><<<ggrid, 256, GM_SMEM>>>(v, wt + 2 * DIM * DIM, xv);

    dim3 agrid(SEQ / BQ, BATCH * NHEADS); // (16, 64)
    attn_tc<<<agrid, 256, AT_SMEM_BYTES>>>(xq, xk, xv, xo);

    gemm_mma<false, true, false><<<ggrid, 256, GM_SMEM>>>(xo, wt + 3 * DIM * DIM, out);
}